// round 5
// baseline (speedup 1.0000x reference)
#include <cuda_runtime.h>
#include <math.h>

// Problem constants
#define B_  2
#define S_  2048
#define D_  640        // = H_*DH_
#define H_  8
#define DH_ 80
#define M_  (B_*S_)    // 4096

// Scratch (device globals — no allocations allowed)
static __device__ float g_q[M_*D_];
static __device__ float g_k[M_*D_];
static __device__ float g_v[M_*D_];
static __device__ float g_attn[M_*D_];

// ---------------------------------------------------------------------------
// SGEMM: C[M,N] = A[M,K] @ W[K,N] (+bias), tiles 128x64x8, 256 threads,
// 8x4 per-thread micro-tile. M%128==0, N%64==0, K%8==0 assumed.
// ---------------------------------------------------------------------------
__global__ __launch_bounds__(256) void sgemm128x64(
    const float* __restrict__ A, const float* __restrict__ W,
    const float* __restrict__ bias, float* __restrict__ C,
    int Kdim, int Ndim)
{
    __shared__ float As[8][128];
    __shared__ float Bs[8][64];

    const int tid = threadIdx.x;
    const int tx = tid & 15;        // 16 col-groups of 4
    const int ty = tid >> 4;        // 16 row-groups of 8
    const int bm = blockIdx.y * 128;
    const int bn = blockIdx.x * 64;

    const int arow = tid >> 1;            // 0..127
    const int acol = (tid & 1) * 4;       // 0 or 4
    const int brow = tid >> 5;            // 0..7
    const int bcol = (tid & 31) * 2;      // 0..62

    float acc[8][4];
#pragma unroll
    for (int i = 0; i < 8; i++)
#pragma unroll
        for (int j = 0; j < 4; j++) acc[i][j] = 0.f;

    for (int k0 = 0; k0 < Kdim; k0 += 8) {
        float4 av = *(const float4*)(A + (bm + arow) * Kdim + k0 + acol);
        As[acol + 0][arow] = av.x;
        As[acol + 1][arow] = av.y;
        As[acol + 2][arow] = av.z;
        As[acol + 3][arow] = av.w;
        *(float2*)&Bs[brow][bcol] =
            *(const float2*)(W + (k0 + brow) * Ndim + bn + bcol);
        __syncthreads();

#pragma unroll
        for (int k = 0; k < 8; k++) {
            float a[8], b[4];
            *(float4*)&a[0] = *(const float4*)&As[k][ty * 8];
            *(float4*)&a[4] = *(const float4*)&As[k][ty * 8 + 4];
            *(float4*)&b[0] = *(const float4*)&Bs[k][tx * 4];
#pragma unroll
            for (int i = 0; i < 8; i++)
#pragma unroll
                for (int j = 0; j < 4; j++)
                    acc[i][j] = fmaf(a[i], b[j], acc[i][j]);
        }
        __syncthreads();
    }

    // epilogue
    float4 bv = make_float4(0.f, 0.f, 0.f, 0.f);
    if (bias) bv = *(const float4*)(bias + bn + tx * 4);
#pragma unroll
    for (int i = 0; i < 8; i++) {
        int row = bm + ty * 8 + i;
        float4 o;
        o.x = acc[i][0] + bv.x;
        o.y = acc[i][1] + bv.y;
        o.z = acc[i][2] + bv.z;
        o.w = acc[i][3] + bv.w;
        *(float4*)(C + row * Ndim + bn + tx * 4) = o;
    }
}

// ---------------------------------------------------------------------------
// Flash attention (fp32, online softmax).
// Grid: (S/64, H, B), 256 threads.
// Q/K tiles: 64 rows x 80, stored row-major with 8-row XOR swizzle on the
// float4 column index, row stride 96 floats (24 float4 slots).
// ---------------------------------------------------------------------------
#define BMQ 64
#define BNK 64
#define QK_STR 96   // floats per swizzled Q/K row
#define VS_STR 84   // floats per V row (80 + pad, float4-aligned)
#define PS_STR 65   // floats per P row (odd -> conflict-free scalar stores)
#define ATTN_SMEM_FLOATS (BMQ*QK_STR + BNK*QK_STR + BNK*VS_STR + BNK*PS_STR)
#define ATTN_SMEM_BYTES (ATTN_SMEM_FLOATS * 4)

__global__ __launch_bounds__(256) void flash_attn_kernel()
{
    extern __shared__ float sm[];
    float* Qs = sm;                       // 64*96
    float* Ks = Qs + BMQ * QK_STR;        // 64*96
    float* Vs = Ks + BNK * QK_STR;        // 64*84
    float* Ps = Vs + BNK * VS_STR;        // 64*65  (P transposed: [kv][q])

    const int tid = threadIdx.x;
    const int tx = tid & 15;   // kv-col group (4) in S-phase; out-col group (5) in PV
    const int ty = tid >> 4;   // q-row group (4)
    const int q0 = blockIdx.x * BMQ;
    const int h  = blockIdx.y;
    const int b  = blockIdx.z;

    const float SCALE = 0.11180339887498949f;  // 80^-0.5

    const float* qg = g_q + (b * S_ + q0) * D_ + h * DH_;
    const float* kg = g_k + (b * S_) * D_ + h * DH_;
    const float* vg = g_v + (b * S_) * D_ + h * DH_;

    // Load Q tile (swizzled)
    for (int idx = tid; idx < BMQ * 20; idx += 256) {
        int r = idx / 20, c4 = idx % 20;
        float4 v = *(const float4*)(qg + r * D_ + c4 * 4);
        *(float4*)&Qs[r * QK_STR + (c4 ^ (r & 7)) * 4] = v;
    }

    float m[4], l[4], o[4][5];
#pragma unroll
    for (int i = 0; i < 4; i++) {
        m[i] = -INFINITY;
        l[i] = 0.f;
#pragma unroll
        for (int j = 0; j < 5; j++) o[i][j] = 0.f;
    }

    for (int t = 0; t < S_ / BNK; t++) {
        const int kv0 = t * BNK;
        __syncthreads();  // previous iteration's reads of Ks/Vs/Ps done
        // Load K (swizzled) and V (plain) tiles
        for (int idx = tid; idx < BNK * 20; idx += 256) {
            int r = idx / 20, c4 = idx % 20;
            const float* rowk = kg + (kv0 + r) * D_ + c4 * 4;
            const float* rowv = vg + (kv0 + r) * D_ + c4 * 4;
            *(float4*)&Ks[r * QK_STR + (c4 ^ (r & 7)) * 4] = *(const float4*)rowk;
            *(float4*)&Vs[r * VS_STR + c4 * 4] = *(const float4*)rowv;
        }
        __syncthreads();

        // S = Q K^T  (4x4 per thread over the 64x64 tile)
        float s[4][4];
#pragma unroll
        for (int i = 0; i < 4; i++)
#pragma unroll
            for (int j = 0; j < 4; j++) s[i][j] = 0.f;

#pragma unroll 4
        for (int d4 = 0; d4 < 20; d4++) {
            float4 a[4], bb[4];
#pragma unroll
            for (int i = 0; i < 4; i++) {
                int r = ty * 4 + i;
                a[i] = *(const float4*)&Qs[r * QK_STR + ((d4 ^ (r & 7)) * 4)];
            }
#pragma unroll
            for (int j = 0; j < 4; j++) {
                int c = tx * 4 + j;
                bb[j] = *(const float4*)&Ks[c * QK_STR + ((d4 ^ (c & 7)) * 4)];
            }
#pragma unroll
            for (int i = 0; i < 4; i++)
#pragma unroll
                for (int j = 0; j < 4; j++) {
                    s[i][j] = fmaf(a[i].x, bb[j].x, s[i][j]);
                    s[i][j] = fmaf(a[i].y, bb[j].y, s[i][j]);
                    s[i][j] = fmaf(a[i].z, bb[j].z, s[i][j]);
                    s[i][j] = fmaf(a[i].w, bb[j].w, s[i][j]);
                }
        }

        // Online softmax: stats shared across the 16 tx lanes of each row.
        float mnew[4], corr[4];
#pragma unroll
        for (int i = 0; i < 4; i++) {
#pragma unroll
            for (int j = 0; j < 4; j++) s[i][j] *= SCALE;
            float mt = fmaxf(fmaxf(s[i][0], s[i][1]), fmaxf(s[i][2], s[i][3]));
#pragma unroll
            for (int off = 8; off > 0; off >>= 1)
                mt = fmaxf(mt, __shfl_xor_sync(0xffffffffu, mt, off));
            mnew[i] = fmaxf(m[i], mt);
            corr[i] = __expf(m[i] - mnew[i]);
            m[i] = mnew[i];
        }
#pragma unroll
        for (int i = 0; i < 4; i++) {
            float rs = 0.f;
#pragma unroll
            for (int j = 0; j < 4; j++) {
                float p = __expf(s[i][j] - mnew[i]);
                s[i][j] = p;
                rs += p;
            }
#pragma unroll
            for (int off = 8; off > 0; off >>= 1)
                rs += __shfl_xor_sync(0xffffffffu, rs, off);
            l[i] = l[i] * corr[i] + rs;
#pragma unroll
            for (int jj = 0; jj < 5; jj++) o[i][jj] *= corr[i];
        }

        // Write P transposed: Ps[kv][q]
#pragma unroll
        for (int j = 0; j < 4; j++)
#pragma unroll
            for (int i = 0; i < 4; i++)
                Ps[(tx * 4 + j) * PS_STR + ty * 4 + i] = s[i][j];
        __syncthreads();

        // O += P V  (rows ty*4+i, cols tx*5+jj)
#pragma unroll 4
        for (int k = 0; k < BNK; k++) {
            float pv[4], vv[5];
#pragma unroll
            for (int i = 0; i < 4; i++) pv[i] = Ps[k * PS_STR + ty * 4 + i];
#pragma unroll
            for (int jj = 0; jj < 5; jj++) vv[jj] = Vs[k * VS_STR + tx * 5 + jj];
#pragma unroll
            for (int i = 0; i < 4; i++)
#pragma unroll
                for (int jj = 0; jj < 5; jj++)
                    o[i][jj] = fmaf(pv[i], vv[jj], o[i][jj]);
        }
    }

    // Epilogue: normalize and store to [B,S,H*DH]
    float* og = g_attn + (b * S_ + q0) * D_ + h * DH_;
#pragma unroll
    for (int i = 0; i < 4; i++) {
        float inv = 1.0f / l[i];
#pragma unroll
        for (int jj = 0; jj < 5; jj++)
            og[(ty * 4 + i) * D_ + tx * 5 + jj] = o[i][jj] * inv;
    }
}

// ---------------------------------------------------------------------------
extern "C" void kernel_launch(void* const* d_in, const int* in_sizes, int n_in,
                              void* d_out, int out_size)
{
    const float* x   = (const float*)d_in[0];
    const float* enc = (const float*)d_in[1];
    const float* Wq  = (const float*)d_in[2];
    const float* Wk  = (const float*)d_in[3];
    const float* Wv  = (const float*)d_in[4];
    const float* Wo  = (const float*)d_in[5];
    const float* bo  = (const float*)d_in[6];
    float* out = (float*)d_out;

    float *qp, *kp, *vp, *ap;
    cudaGetSymbolAddress((void**)&qp, g_q);
    cudaGetSymbolAddress((void**)&kp, g_k);
    cudaGetSymbolAddress((void**)&vp, g_v);
    cudaGetSymbolAddress((void**)&ap, g_attn);

    cudaFuncSetAttribute(flash_attn_kernel,
                         cudaFuncAttributeMaxDynamicSharedMemorySize,
                         ATTN_SMEM_BYTES);

    dim3 gemm_grid(D_ / 64, M_ / 128);   // (10, 32)
    sgemm128x64<<<gemm_grid, 256>>>(x,   Wq, nullptr, qp, D_, D_);
    sgemm128x64<<<gemm_grid, 256>>>(enc, Wk, nullptr, kp, D_, D_);
    sgemm128x64<<<gemm_grid, 256>>>(enc, Wv, nullptr, vp, D_, D_);

    dim3 attn_grid(S_ / BMQ, H_, B_);    // (32, 8, 2)
    flash_attn_kernel<<<attn_grid, 256, ATTN_SMEM_BYTES>>>();

    sgemm128x64<<<gemm_grid, 256>>>(ap, Wo, bo, out, D_, D_);
}

// round 6
// speedup vs baseline: 1.8773x; 1.8773x over previous
#include <cuda_runtime.h>
#include <math.h>

// Problem constants
#define B_  2
#define S_  2048
#define D_  640        // = H_*DH_
#define H_  8
#define DH_ 80
#define M_  (B_*S_)    // 4096

// Scratch (device globals — no allocations allowed)
static __device__ float g_q[M_*D_];
static __device__ float g_k[M_*D_];
static __device__ float g_v[M_*D_];
static __device__ float g_attn[M_*D_];

// ---------------------------------------------------------------------------
// SGEMM: C[M,N] = A[M,K] @ W[K,N] (+bias), tiles 128x64x8, 256 threads,
// 8x4 per-thread micro-tile. M%128==0, N%64==0, K%8==0 assumed.
// ---------------------------------------------------------------------------
__global__ __launch_bounds__(256) void sgemm128x64(
    const float* __restrict__ A, const float* __restrict__ W,
    const float* __restrict__ bias, float* __restrict__ C,
    int Kdim, int Ndim)
{
    __shared__ float As[8][128];
    __shared__ float Bs[8][64];

    const int tid = threadIdx.x;
    const int tx = tid & 15;        // 16 col-groups of 4
    const int ty = tid >> 4;        // 16 row-groups of 8
    const int bm = blockIdx.y * 128;
    const int bn = blockIdx.x * 64;

    const int arow = tid >> 1;            // 0..127
    const int acol = (tid & 1) * 4;       // 0 or 4
    const int brow = tid >> 5;            // 0..7
    const int bcol = (tid & 31) * 2;      // 0..62

    float acc[8][4];
#pragma unroll
    for (int i = 0; i < 8; i++)
#pragma unroll
        for (int j = 0; j < 4; j++) acc[i][j] = 0.f;

    for (int k0 = 0; k0 < Kdim; k0 += 8) {
        float4 av = *(const float4*)(A + (bm + arow) * Kdim + k0 + acol);
        As[acol + 0][arow] = av.x;
        As[acol + 1][arow] = av.y;
        As[acol + 2][arow] = av.z;
        As[acol + 3][arow] = av.w;
        *(float2*)&Bs[brow][bcol] =
            *(const float2*)(W + (k0 + brow) * Ndim + bn + bcol);
        __syncthreads();

#pragma unroll
        for (int k = 0; k < 8; k++) {
            float a[8], b[4];
            *(float4*)&a[0] = *(const float4*)&As[k][ty * 8];
            *(float4*)&a[4] = *(const float4*)&As[k][ty * 8 + 4];
            *(float4*)&b[0] = *(const float4*)&Bs[k][tx * 4];
#pragma unroll
            for (int i = 0; i < 8; i++)
#pragma unroll
                for (int j = 0; j < 4; j++)
                    acc[i][j] = fmaf(a[i], b[j], acc[i][j]);
        }
        __syncthreads();
    }

    // epilogue
    float4 bv = make_float4(0.f, 0.f, 0.f, 0.f);
    if (bias) bv = *(const float4*)(bias + bn + tx * 4);
#pragma unroll
    for (int i = 0; i < 8; i++) {
        int row = bm + ty * 8 + i;
        float4 o;
        o.x = acc[i][0] + bv.x;
        o.y = acc[i][1] + bv.y;
        o.z = acc[i][2] + bv.z;
        o.w = acc[i][3] + bv.w;
        *(float4*)(C + row * Ndim + bn + tx * 4) = o;
    }
}

// ---------------------------------------------------------------------------
// Flash attention (fp32, online softmax).
// Grid: (S/64, H, B), 256 threads.
// Q/K tiles: 64 rows x 80, stored row-major with 8-row XOR swizzle on the
// float4 column index, row stride 96 floats (24 float4 slots).
// ---------------------------------------------------------------------------
#define BMQ 64
#define BNK 64
#define QK_STR 96   // floats per swizzled Q/K row
#define VS_STR 84   // floats per V row (80 + pad, float4-aligned)
#define PS_STR 65   // floats per P row (odd -> conflict-free scalar stores)
#define ATTN_SMEM_FLOATS (BMQ*QK_STR + BNK*QK_STR + BNK*VS_STR + BNK*PS_STR)
#define ATTN_SMEM_BYTES (ATTN_SMEM_FLOATS * 4)

__global__ __launch_bounds__(256) void flash_attn_kernel()
{
    extern __shared__ float sm[];
    float* Qs = sm;                       // 64*96
    float* Ks = Qs + BMQ * QK_STR;        // 64*96
    float* Vs = Ks + BNK * QK_STR;        // 64*84
    float* Ps = Vs + BNK * VS_STR;        // 64*65  (P transposed: [kv][q])

    const int tid = threadIdx.x;
    const int tx = tid & 15;   // kv-col group (4) in S-phase; out-col group (5) in PV
    const int ty = tid >> 4;   // q-row group (4)
    const int q0 = blockIdx.x * BMQ;
    const int h  = blockIdx.y;
    const int b  = blockIdx.z;

    const float SCALE = 0.11180339887498949f;  // 80^-0.5

    const float* qg = g_q + (b * S_ + q0) * D_ + h * DH_;
    const float* kg = g_k + (b * S_) * D_ + h * DH_;
    const float* vg = g_v + (b * S_) * D_ + h * DH_;

    // Load Q tile (swizzled)
    for (int idx = tid; idx < BMQ * 20; idx += 256) {
        int r = idx / 20, c4 = idx % 20;
        float4 v = *(const float4*)(qg + r * D_ + c4 * 4);
        *(float4*)&Qs[r * QK_STR + (c4 ^ (r & 7)) * 4] = v;
    }

    float m[4], l[4], o[4][5];
#pragma unroll
    for (int i = 0; i < 4; i++) {
        m[i] = -INFINITY;
        l[i] = 0.f;
#pragma unroll
        for (int j = 0; j < 5; j++) o[i][j] = 0.f;
    }

    for (int t = 0; t < S_ / BNK; t++) {
        const int kv0 = t * BNK;
        __syncthreads();  // previous iteration's reads of Ks/Vs/Ps done
        // Load K (swizzled) and V (plain) tiles
        for (int idx = tid; idx < BNK * 20; idx += 256) {
            int r = idx / 20, c4 = idx % 20;
            const float* rowk = kg + (kv0 + r) * D_ + c4 * 4;
            const float* rowv = vg + (kv0 + r) * D_ + c4 * 4;
            *(float4*)&Ks[r * QK_STR + (c4 ^ (r & 7)) * 4] = *(const float4*)rowk;
            *(float4*)&Vs[r * VS_STR + c4 * 4] = *(const float4*)rowv;
        }
        __syncthreads();

        // S = Q K^T  (4x4 per thread over the 64x64 tile)
        float s[4][4];
#pragma unroll
        for (int i = 0; i < 4; i++)
#pragma unroll
            for (int j = 0; j < 4; j++) s[i][j] = 0.f;

#pragma unroll 4
        for (int d4 = 0; d4 < 20; d4++) {
            float4 a[4], bb[4];
#pragma unroll
            for (int i = 0; i < 4; i++) {
                int r = ty * 4 + i;
                a[i] = *(const float4*)&Qs[r * QK_STR + ((d4 ^ (r & 7)) * 4)];
            }
#pragma unroll
            for (int j = 0; j < 4; j++) {
                int c = tx * 4 + j;
                bb[j] = *(const float4*)&Ks[c * QK_STR + ((d4 ^ (c & 7)) * 4)];
            }
#pragma unroll
            for (int i = 0; i < 4; i++)
#pragma unroll
                for (int j = 0; j < 4; j++) {
                    s[i][j] = fmaf(a[i].x, bb[j].x, s[i][j]);
                    s[i][j] = fmaf(a[i].y, bb[j].y, s[i][j]);
                    s[i][j] = fmaf(a[i].z, bb[j].z, s[i][j]);
                    s[i][j] = fmaf(a[i].w, bb[j].w, s[i][j]);
                }
        }

        // Online softmax: stats shared across the 16 tx lanes of each row.
        float mnew[4], corr[4];
#pragma unroll
        for (int i = 0; i < 4; i++) {
#pragma unroll
            for (int j = 0; j < 4; j++) s[i][j] *= SCALE;
            float mt = fmaxf(fmaxf(s[i][0], s[i][1]), fmaxf(s[i][2], s[i][3]));
#pragma unroll
            for (int off = 8; off > 0; off >>= 1)
                mt = fmaxf(mt, __shfl_xor_sync(0xffffffffu, mt, off));
            mnew[i] = fmaxf(m[i], mt);
            corr[i] = __expf(m[i] - mnew[i]);
            m[i] = mnew[i];
        }
#pragma unroll
        for (int i = 0; i < 4; i++) {
            float rs = 0.f;
#pragma unroll
            for (int j = 0; j < 4; j++) {
                float p = __expf(s[i][j] - mnew[i]);
                s[i][j] = p;
                rs += p;
            }
#pragma unroll
            for (int off = 8; off > 0; off >>= 1)
                rs += __shfl_xor_sync(0xffffffffu, rs, off);
            l[i] = l[i] * corr[i] + rs;
#pragma unroll
            for (int jj = 0; jj < 5; jj++) o[i][jj] *= corr[i];
        }

        // Write P transposed: Ps[kv][q]
#pragma unroll
        for (int j = 0; j < 4; j++)
#pragma unroll
            for (int i = 0; i < 4; i++)
                Ps[(tx * 4 + j) * PS_STR + ty * 4 + i] = s[i][j];
        __syncthreads();

        // O += P V  (rows ty*4+i, cols tx*5+jj)
#pragma unroll 4
        for (int k = 0; k < BNK; k++) {
            float pv[4], vv[5];
#pragma unroll
            for (int i = 0; i < 4; i++) pv[i] = Ps[k * PS_STR + ty * 4 + i];
#pragma unroll
            for (int jj = 0; jj < 5; jj++) vv[jj] = Vs[k * VS_STR + tx * 5 + jj];
#pragma unroll
            for (int i = 0; i < 4; i++)
#pragma unroll
                for (int jj = 0; jj < 5; jj++)
                    o[i][jj] = fmaf(pv[i], vv[jj], o[i][jj]);
        }
    }

    // Epilogue: normalize and store to [B,S,H*DH]
    float* og = g_attn + (b * S_ + q0) * D_ + h * DH_;
#pragma unroll
    for (int i = 0; i < 4; i++) {
        float inv = 1.0f / l[i];
#pragma unroll
        for (int jj = 0; jj < 5; jj++)
            og[(ty * 4 + i) * D_ + tx * 5 + jj] = o[i][jj] * inv;
    }
}

// ---------------------------------------------------------------------------
extern "C" void kernel_launch(void* const* d_in, const int* in_sizes, int n_in,
                              void* d_out, int out_size)
{
    const float* x   = (const float*)d_in[0];
    const float* enc = (const float*)d_in[1];
    const float* Wq  = (const float*)d_in[2];
    const float* Wk  = (const float*)d_in[3];
    const float* Wv  = (const float*)d_in[4];
    const float* Wo  = (const float*)d_in[5];
    const float* bo  = (const float*)d_in[6];
    float* out = (float*)d_out;

    float *qp, *kp, *vp, *ap;
    cudaGetSymbolAddress((void**)&qp, g_q);
    cudaGetSymbolAddress((void**)&kp, g_k);
    cudaGetSymbolAddress((void**)&vp, g_v);
    cudaGetSymbolAddress((void**)&ap, g_attn);

    cudaFuncSetAttribute(flash_attn_kernel,
                         cudaFuncAttributeMaxDynamicSharedMemorySize,
                         ATTN_SMEM_BYTES);

    dim3 gemm_grid(D_ / 64, M_ / 128);   // (10, 32)
    sgemm128x64<<<gemm_grid, 256>>>(x,   Wq, nullptr, qp, D_, D_);
    sgemm128x64<<<gemm_grid, 256>>>(enc, Wk, nullptr, kp, D_, D_);
    sgemm128x64<<<gemm_grid, 256>>>(enc, Wv, nullptr, vp, D_, D_);

    dim3 attn_grid(S_ / BMQ, H_, B_);    // (32, 8, 2)
    flash_attn_kernel<<<attn_grid, 256, ATTN_SMEM_BYTES>>>();

    sgemm128x64<<<gemm_grid, 256>>>(ap, Wo, bo, out, D_, D_);
}

// round 9
// speedup vs baseline: 1.8807x; 1.0018x over previous
#include <cuda_runtime.h>
#include <math.h>

// Problem constants
#define B_  2
#define S_  2048
#define D_  640        // = H_*DH_
#define H_  8
#define DH_ 80
#define M_  (B_*S_)    // 4096

// Scratch (device globals — no allocations allowed)
static __device__ float g_q[M_*D_];
static __device__ float g_k[M_*D_];
static __device__ float g_v[M_*D_];
static __device__ float g_attn[M_*D_];

// ---------------------------------------------------------------------------
// SGEMM: C[M,N] = A[M,K] @ W[K,N] (+bias), tiles 128x64x8, 256 threads,
// 8x4 per-thread micro-tile. (Already at the fp32 FFMA floor — unchanged.)
// ---------------------------------------------------------------------------
__global__ __launch_bounds__(256) void sgemm128x64(
    const float* __restrict__ A, const float* __restrict__ W,
    const float* __restrict__ bias, float* __restrict__ C,
    int Kdim, int Ndim)
{
    __shared__ float As[8][128];
    __shared__ float Bs[8][64];

    const int tid = threadIdx.x;
    const int tx = tid & 15;
    const int ty = tid >> 4;
    const int bm = blockIdx.y * 128;
    const int bn = blockIdx.x * 64;

    const int arow = tid >> 1;
    const int acol = (tid & 1) * 4;
    const int brow = tid >> 5;
    const int bcol = (tid & 31) * 2;

    float acc[8][4];
#pragma unroll
    for (int i = 0; i < 8; i++)
#pragma unroll
        for (int j = 0; j < 4; j++) acc[i][j] = 0.f;

    for (int k0 = 0; k0 < Kdim; k0 += 8) {
        float4 av = *(const float4*)(A + (bm + arow) * Kdim + k0 + acol);
        As[acol + 0][arow] = av.x;
        As[acol + 1][arow] = av.y;
        As[acol + 2][arow] = av.z;
        As[acol + 3][arow] = av.w;
        *(float2*)&Bs[brow][bcol] =
            *(const float2*)(W + (k0 + brow) * Ndim + bn + bcol);
        __syncthreads();

#pragma unroll
        for (int k = 0; k < 8; k++) {
            float a[8], b[4];
            *(float4*)&a[0] = *(const float4*)&As[k][ty * 8];
            *(float4*)&a[4] = *(const float4*)&As[k][ty * 8 + 4];
            *(float4*)&b[0] = *(const float4*)&Bs[k][tx * 4];
#pragma unroll
            for (int i = 0; i < 8; i++)
#pragma unroll
                for (int j = 0; j < 4; j++)
                    acc[i][j] = fmaf(a[i], b[j], acc[i][j]);
        }
        __syncthreads();
    }

    float4 bv = make_float4(0.f, 0.f, 0.f, 0.f);
    if (bias) bv = *(const float4*)(bias + bn + tx * 4);
#pragma unroll
    for (int i = 0; i < 8; i++) {
        int row = bm + ty * 8 + i;
        float4 o;
        o.x = acc[i][0] + bv.x;
        o.y = acc[i][1] + bv.y;
        o.z = acc[i][2] + bv.z;
        o.w = acc[i][3] + bv.w;
        *(float4*)(C + row * Ndim + bn + tx * 4) = o;
    }
}

// ---------------------------------------------------------------------------
// Flash attention (fp32, online softmax, exp2 domain).
// Grid: (S/64, H, B), 256 threads.
// Q/K tiles: 64 x 80, row stride 96, 8-row XOR swizzle on float4 index
// (conflict-free, unchanged).
// P tile: transposed [kv][q], stride 68 floats -> float4-aligned broadcast
// loads in PV.
// V tile: row-major stride 84; PV output cols split as tx*4+jj (float4 load)
// plus tail col 64+tx (scalar, conflict-free).
// ---------------------------------------------------------------------------
#define BMQ 64
#define BNK 64
#define QK_STR 96   // floats per swizzled Q/K row
#define VS_STR 84   // floats per V row (80 + pad, float4-aligned)
#define PS_STR 68   // floats per P row ([kv][q]), float4-aligned, 2-way max
#define ATTN_SMEM_FLOATS (BMQ*QK_STR + BNK*QK_STR + BNK*VS_STR + BNK*PS_STR)
#define ATTN_SMEM_BYTES (ATTN_SMEM_FLOATS * 4)

__global__ __launch_bounds__(256) void flash_attn_kernel()
{
    extern __shared__ float sm[];
    float* Qs = sm;                       // 64*96
    float* Ks = Qs + BMQ * QK_STR;        // 64*96
    float* Vs = Ks + BNK * QK_STR;        // 64*84
    float* Ps = Vs + BNK * VS_STR;        // 64*68  (P transposed: [kv][q])

    const int tid = threadIdx.x;
    const int tx = tid & 15;   // kv-col group (4) in S-phase; dh-col group in PV
    const int ty = tid >> 4;   // q-row group (4)
    const int q0 = blockIdx.x * BMQ;
    const int h  = blockIdx.y;
    const int b  = blockIdx.z;

    // SCALE * log2(e): softmax computed in exp2 domain (invariant under the
    // per-row shift; MUFU.EX2 directly, no FMUL per score).
    const float QSCALE = 0.11180339887498949f * 1.4426950408889634f;

    const float* qg = g_q + (b * S_ + q0) * D_ + h * DH_;
    const float* kg = g_k + (b * S_) * D_ + h * DH_;
    const float* vg = g_v + (b * S_) * D_ + h * DH_;

    // Load Q tile (swizzled), scale folded in
    for (int idx = tid; idx < BMQ * 20; idx += 256) {
        int r = idx / 20, c4 = idx % 20;
        float4 v = *(const float4*)(qg + r * D_ + c4 * 4);
        v.x *= QSCALE; v.y *= QSCALE; v.z *= QSCALE; v.w *= QSCALE;
        *(float4*)&Qs[r * QK_STR + (c4 ^ (r & 7)) * 4] = v;
    }

    float m[4], l[4], o4[4][4], o1[4];
#pragma unroll
    for (int i = 0; i < 4; i++) {
        m[i] = -INFINITY;
        l[i] = 0.f;
        o1[i] = 0.f;
#pragma unroll
        for (int j = 0; j < 4; j++) o4[i][j] = 0.f;
    }

    for (int t = 0; t < S_ / BNK; t++) {
        const int kv0 = t * BNK;
        __syncthreads();  // previous iteration's reads of Ks/Vs/Ps done
        // Load K (swizzled) and V (plain) tiles
        for (int idx = tid; idx < BNK * 20; idx += 256) {
            int r = idx / 20, c4 = idx % 20;
            const float* rowk = kg + (kv0 + r) * D_ + c4 * 4;
            const float* rowv = vg + (kv0 + r) * D_ + c4 * 4;
            *(float4*)&Ks[r * QK_STR + (c4 ^ (r & 7)) * 4] = *(const float4*)rowk;
            *(float4*)&Vs[r * VS_STR + c4 * 4] = *(const float4*)rowv;
        }
        __syncthreads();

        // S = Q K^T  (4x4 per thread over the 64x64 tile)
        float s[4][4];
#pragma unroll
        for (int i = 0; i < 4; i++)
#pragma unroll
            for (int j = 0; j < 4; j++) s[i][j] = 0.f;

#pragma unroll 4
        for (int d4 = 0; d4 < 20; d4++) {
            float4 a[4], bb[4];
#pragma unroll
            for (int i = 0; i < 4; i++) {
                int r = ty * 4 + i;
                a[i] = *(const float4*)&Qs[r * QK_STR + ((d4 ^ (r & 7)) * 4)];
            }
#pragma unroll
            for (int j = 0; j < 4; j++) {
                int c = tx * 4 + j;
                bb[j] = *(const float4*)&Ks[c * QK_STR + ((d4 ^ (c & 7)) * 4)];
            }
#pragma unroll
            for (int i = 0; i < 4; i++)
#pragma unroll
                for (int j = 0; j < 4; j++) {
                    s[i][j] = fmaf(a[i].x, bb[j].x, s[i][j]);
                    s[i][j] = fmaf(a[i].y, bb[j].y, s[i][j]);
                    s[i][j] = fmaf(a[i].z, bb[j].z, s[i][j]);
                    s[i][j] = fmaf(a[i].w, bb[j].w, s[i][j]);
                }
        }

        // Online softmax (exp2 domain); stats shared across the 16 tx lanes.
        float mnew[4], corr[4];
#pragma unroll
        for (int i = 0; i < 4; i++) {
            float mt = fmaxf(fmaxf(s[i][0], s[i][1]), fmaxf(s[i][2], s[i][3]));
#pragma unroll
            for (int off = 8; off > 0; off >>= 1)
                mt = fmaxf(mt, __shfl_xor_sync(0xffffffffu, mt, off));
            mnew[i] = fmaxf(m[i], mt);
            corr[i] = exp2f(m[i] - mnew[i]);
            m[i] = mnew[i];
        }
#pragma unroll
        for (int i = 0; i < 4; i++) {
            float rs = 0.f;
#pragma unroll
            for (int j = 0; j < 4; j++) {
                float p = exp2f(s[i][j] - mnew[i]);
                s[i][j] = p;
                rs += p;
            }
#pragma unroll
            for (int off = 8; off > 0; off >>= 1)
                rs += __shfl_xor_sync(0xffffffffu, rs, off);
            l[i] = l[i] * corr[i] + rs;
#pragma unroll
            for (int jj = 0; jj < 4; jj++) o4[i][jj] *= corr[i];
            o1[i] *= corr[i];
        }

        // Write P transposed: Ps[kv][q] (stride 68 -> PV loads are LDS.128)
#pragma unroll
        for (int j = 0; j < 4; j++)
#pragma unroll
            for (int i = 0; i < 4; i++)
                Ps[(tx * 4 + j) * PS_STR + ty * 4 + i] = s[i][j];
        __syncthreads();

        // O += P V
        // per k: 1 broadcast LDS.128 (P rows), 1 LDS.128 (V cols tx*4),
        //        1 LDS.32 (V col 64+tx) -> 3 shared-mem instr / 20 FMA.
#pragma unroll 4
        for (int k = 0; k < BNK; k++) {
            float4 p  = *(const float4*)&Ps[k * PS_STR + ty * 4];
            float4 vv = *(const float4*)&Vs[k * VS_STR + tx * 4];
            float  v1 = Vs[k * VS_STR + 64 + tx];
            float pr[4] = {p.x, p.y, p.z, p.w};
#pragma unroll
            for (int i = 0; i < 4; i++) {
                o4[i][0] = fmaf(pr[i], vv.x, o4[i][0]);
                o4[i][1] = fmaf(pr[i], vv.y, o4[i][1]);
                o4[i][2] = fmaf(pr[i], vv.z, o4[i][2]);
                o4[i][3] = fmaf(pr[i], vv.w, o4[i][3]);
                o1[i]    = fmaf(pr[i], v1,   o1[i]);
            }
        }
    }

    // Epilogue: normalize and store to [B,S,H*DH]
    float* og = g_attn + (b * S_ + q0) * D_ + h * DH_;
#pragma unroll
    for (int i = 0; i < 4; i++) {
        float inv = 1.0f / l[i];
        float4 o;
        o.x = o4[i][0] * inv;
        o.y = o4[i][1] * inv;
        o.z = o4[i][2] * inv;
        o.w = o4[i][3] * inv;
        *(float4*)(og + (ty * 4 + i) * D_ + tx * 4) = o;
        og[(ty * 4 + i) * D_ + 64 + tx] = o1[i] * inv;
    }
}

// ---------------------------------------------------------------------------
extern "C" void kernel_launch(void* const* d_in, const int* in_sizes, int n_in,
                              void* d_out, int out_size)
{
    const float* x   = (const float*)d_in[0];
    const float* enc = (const float*)d_in[1];
    const float* Wq  = (const float*)d_in[2];
    const float* Wk  = (const float*)d_in[3];
    const float* Wv  = (const float*)d_in[4];
    const float* Wo  = (const float*)d_in[5];
    const float* bo  = (const float*)d_in[6];
    float* out = (float*)d_out;

    float *qp, *kp, *vp, *ap;
    cudaGetSymbolAddress((void**)&qp, g_q);
    cudaGetSymbolAddress((void**)&kp, g_k);
    cudaGetSymbolAddress((void**)&vp, g_v);
    cudaGetSymbolAddress((void**)&ap, g_attn);

    cudaFuncSetAttribute(flash_attn_kernel,
                         cudaFuncAttributeMaxDynamicSharedMemorySize,
                         ATTN_SMEM_BYTES);

    dim3 gemm_grid(D_ / 64, M_ / 128);   // (10, 32)
    sgemm128x64<<<gemm_grid, 256>>>(x,   Wq, nullptr, qp, D_, D_);
    sgemm128x64<<<gemm_grid, 256>>>(enc, Wk, nullptr, kp, D_, D_);
    sgemm128x64<<<gemm_grid, 256>>>(enc, Wv, nullptr, vp, D_, D_);

    dim3 attn_grid(S_ / BMQ, H_, B_);    // (32, 8, 2)
    flash_attn_kernel<<<attn_grid, 256, ATTN_SMEM_BYTES>>>();

    sgemm128x64<<<gemm_grid, 256>>>(ap, Wo, bo, out, D_, D_);
}

// round 11
// speedup vs baseline: 4.1884x; 2.2270x over previous
#include <cuda_runtime.h>
#include <math.h>
#include <stdint.h>

// Problem constants
#define B_  2
#define S_  2048
#define D_  640        // = H_*DH_
#define H_  8
#define DH_ 80
#define M_  (B_*S_)    // 4096

// Scratch (device globals — no allocations allowed)
static __device__ float g_q[M_*D_];
static __device__ float g_k[M_*D_];
static __device__ float g_v[M_*D_];
static __device__ float g_attn[M_*D_];

// ---------------------------------------------------------------------------
// SGEMM: C[M,N] = A[M,K] @ W[K,N] (+bias), tiles 128x64x8, 256 threads,
// 8x4 per-thread micro-tile. (At the fp32 FFMA floor — unchanged this round.)
// ---------------------------------------------------------------------------
__global__ __launch_bounds__(256) void sgemm128x64(
    const float* __restrict__ A, const float* __restrict__ W,
    const float* __restrict__ bias, float* __restrict__ C,
    int Kdim, int Ndim)
{
    __shared__ float As[8][128];
    __shared__ float Bs[8][64];

    const int tid = threadIdx.x;
    const int tx = tid & 15;
    const int ty = tid >> 4;
    const int bm = blockIdx.y * 128;
    const int bn = blockIdx.x * 64;

    const int arow = tid >> 1;
    const int acol = (tid & 1) * 4;
    const int brow = tid >> 5;
    const int bcol = (tid & 31) * 2;

    float acc[8][4];
#pragma unroll
    for (int i = 0; i < 8; i++)
#pragma unroll
        for (int j = 0; j < 4; j++) acc[i][j] = 0.f;

    for (int k0 = 0; k0 < Kdim; k0 += 8) {
        float4 av = *(const float4*)(A + (bm + arow) * Kdim + k0 + acol);
        As[acol + 0][arow] = av.x;
        As[acol + 1][arow] = av.y;
        As[acol + 2][arow] = av.z;
        As[acol + 3][arow] = av.w;
        *(float2*)&Bs[brow][bcol] =
            *(const float2*)(W + (k0 + brow) * Ndim + bn + bcol);
        __syncthreads();

#pragma unroll
        for (int k = 0; k < 8; k++) {
            float a[8], b[4];
            *(float4*)&a[0] = *(const float4*)&As[k][ty * 8];
            *(float4*)&a[4] = *(const float4*)&As[k][ty * 8 + 4];
            *(float4*)&b[0] = *(const float4*)&Bs[k][tx * 4];
#pragma unroll
            for (int i = 0; i < 8; i++)
#pragma unroll
                for (int j = 0; j < 4; j++)
                    acc[i][j] = fmaf(a[i], b[j], acc[i][j]);
        }
        __syncthreads();
    }

    float4 bv = make_float4(0.f, 0.f, 0.f, 0.f);
    if (bias) bv = *(const float4*)(bias + bn + tx * 4);
#pragma unroll
    for (int i = 0; i < 8; i++) {
        int row = bm + ty * 8 + i;
        float4 o;
        o.x = acc[i][0] + bv.x;
        o.y = acc[i][1] + bv.y;
        o.z = acc[i][2] + bv.z;
        o.w = acc[i][3] + bv.w;
        *(float4*)(C + row * Ndim + bn + tx * 4) = o;
    }
}

// ---------------------------------------------------------------------------
// Tensor-core flash attention (tf32 mma.sync, fp32 accumulate, exp2 softmax).
// Grid: (S/128, H, B), 256 threads = 8 warps.
// Warp w owns q rows [w*16, w*16+16), full 64-kv tile width -> warp-local
// softmax, register-resident P (C-frag -> A-frag via shuffles).
// K smem stride 84, V stride 88: both conflict-free for the B-frag patterns.
// ---------------------------------------------------------------------------
#define BMQ 128
#define BNK 64
#define KST 84
#define VST 88

__device__ __forceinline__ float to_tf32(float x) {
    uint32_t u;
    asm("cvt.rna.tf32.f32 %0, %1;" : "=r"(u) : "f"(x));
    return __uint_as_float(u);
}

__device__ __forceinline__ float ex2(float x) {
    float r;
    asm("ex2.approx.ftz.f32 %0, %1;" : "=f"(r) : "f"(x));
    return r;
}

__device__ __forceinline__ void mma_tf32(float c[4],
    float a0, float a1, float a2, float a3, float b0, float b1)
{
    asm volatile(
        "mma.sync.aligned.m16n8k8.row.col.f32.tf32.tf32.f32 "
        "{%0,%1,%2,%3}, {%4,%5,%6,%7}, {%8,%9}, {%0,%1,%2,%3};"
        : "+f"(c[0]), "+f"(c[1]), "+f"(c[2]), "+f"(c[3])
        : "r"(__float_as_uint(a0)), "r"(__float_as_uint(a1)),
          "r"(__float_as_uint(a2)), "r"(__float_as_uint(a3)),
          "r"(__float_as_uint(b0)), "r"(__float_as_uint(b1)));
}

__global__ __launch_bounds__(256, 1) void flash_attn_tc()
{
    __shared__ float Ks[BNK * KST];
    __shared__ float Vs[BNK * VST];

    const int tid  = threadIdx.x;
    const int w    = tid >> 5;
    const int lane = tid & 31;
    const int qr   = lane >> 2;   // row-in-group 0..7
    const int qc   = lane & 3;    // quad lane 0..3
    const int q0   = blockIdx.x * BMQ;
    const int h    = blockIdx.y;
    const int b    = blockIdx.z;

    // softmax in exp2 domain: fold SCALE*log2(e) into Q
    const float QS = 0.11180339887498949f * 1.4426950408889634f;

    const float* qg = g_q + (size_t)(b * S_ + q0 + w * 16) * D_ + h * DH_;
    const float* kg = g_k + (size_t)(b * S_) * D_ + h * DH_;
    const float* vg = g_v + (size_t)(b * S_) * D_ + h * DH_;

    // Q fragments (tf32, scale folded) — resident for the whole kernel.
    float qa[10][4];
#pragma unroll
    for (int kb = 0; kb < 10; kb++) {
        qa[kb][0] = to_tf32(qg[(qr    ) * D_ + kb * 8 + qc    ] * QS);
        qa[kb][1] = to_tf32(qg[(qr + 8) * D_ + kb * 8 + qc    ] * QS);
        qa[kb][2] = to_tf32(qg[(qr    ) * D_ + kb * 8 + qc + 4] * QS);
        qa[kb][3] = to_tf32(qg[(qr + 8) * D_ + kb * 8 + qc + 4] * QS);
    }

    float m0 = -INFINITY, m1 = -INFINITY, l0 = 0.f, l1 = 0.f;
    float of[10][4];
#pragma unroll
    for (int n = 0; n < 10; n++)
#pragma unroll
        for (int r = 0; r < 4; r++) of[n][r] = 0.f;

    for (int t = 0; t < S_ / BNK; t++) {
        const int kv0 = t * BNK;
        __syncthreads();   // previous iteration's smem reads complete
        // Load K/V tile (cvt to tf32 on the way in)
        for (int idx = tid; idx < BNK * 20; idx += 256) {
            int r = idx / 20, c4 = (idx % 20) * 4;
            float4 k4 = *(const float4*)(kg + (size_t)(kv0 + r) * D_ + c4);
            float4 v4 = *(const float4*)(vg + (size_t)(kv0 + r) * D_ + c4);
            *(float4*)&Ks[r * KST + c4] = make_float4(
                to_tf32(k4.x), to_tf32(k4.y), to_tf32(k4.z), to_tf32(k4.w));
            *(float4*)&Vs[r * VST + c4] = make_float4(
                to_tf32(v4.x), to_tf32(v4.y), to_tf32(v4.z), to_tf32(v4.w));
        }
        __syncthreads();

        // ---- S = Q K^T : 8 n-blocks x 10 k-blocks of m16n8k8 ----
        float sf[8][4];
#pragma unroll
        for (int n = 0; n < 8; n++)
#pragma unroll
            for (int r = 0; r < 4; r++) sf[n][r] = 0.f;

#pragma unroll
        for (int kb = 0; kb < 10; kb++)
#pragma unroll
            for (int nb = 0; nb < 8; nb++) {
                float b0 = Ks[(nb * 8 + qr) * KST + kb * 8 + qc];
                float b1 = Ks[(nb * 8 + qr) * KST + kb * 8 + qc + 4];
                mma_tf32(sf[nb], qa[kb][0], qa[kb][1], qa[kb][2], qa[kb][3],
                         b0, b1);
            }

        // ---- online softmax (rows g = qr, g+8; full row inside the quad) ----
        float rmax0 = -INFINITY, rmax1 = -INFINITY;
#pragma unroll
        for (int nb = 0; nb < 8; nb++) {
            rmax0 = fmaxf(rmax0, fmaxf(sf[nb][0], sf[nb][1]));
            rmax1 = fmaxf(rmax1, fmaxf(sf[nb][2], sf[nb][3]));
        }
#pragma unroll
        for (int off = 1; off <= 2; off <<= 1) {
            rmax0 = fmaxf(rmax0, __shfl_xor_sync(0xffffffffu, rmax0, off));
            rmax1 = fmaxf(rmax1, __shfl_xor_sync(0xffffffffu, rmax1, off));
        }
        float mn0 = fmaxf(m0, rmax0), mn1 = fmaxf(m1, rmax1);
        float cr0 = ex2(m0 - mn0),    cr1 = ex2(m1 - mn1);
        m0 = mn0; m1 = mn1;

        float rs0 = 0.f, rs1 = 0.f;
#pragma unroll
        for (int nb = 0; nb < 8; nb++) {
            sf[nb][0] = ex2(sf[nb][0] - mn0); rs0 += sf[nb][0];
            sf[nb][1] = ex2(sf[nb][1] - mn0); rs0 += sf[nb][1];
            sf[nb][2] = ex2(sf[nb][2] - mn1); rs1 += sf[nb][2];
            sf[nb][3] = ex2(sf[nb][3] - mn1); rs1 += sf[nb][3];
        }
#pragma unroll
        for (int off = 1; off <= 2; off <<= 1) {
            rs0 += __shfl_xor_sync(0xffffffffu, rs0, off);
            rs1 += __shfl_xor_sync(0xffffffffu, rs1, off);
        }
        l0 = l0 * cr0 + rs0;
        l1 = l1 * cr1 + rs1;
#pragma unroll
        for (int n = 0; n < 10; n++) {
            of[n][0] *= cr0; of[n][1] *= cr0;
            of[n][2] *= cr1; of[n][3] *= cr1;
        }

        // P -> tf32 in place
#pragma unroll
        for (int nb = 0; nb < 8; nb++)
#pragma unroll
            for (int r = 0; r < 4; r++) sf[nb][r] = to_tf32(sf[nb][r]);

        // ---- O += P V : P C-frag -> A-frag via quad shuffles ----
        const int srcA = (lane & ~3) | (qc >> 1);
        const int srcB = srcA + 2;
        const bool odd = qc & 1;
#pragma unroll
        for (int kk = 0; kk < 8; kk++) {
            float t00 = __shfl_sync(0xffffffffu, sf[kk][0], srcA);
            float t01 = __shfl_sync(0xffffffffu, sf[kk][1], srcA);
            float t10 = __shfl_sync(0xffffffffu, sf[kk][2], srcA);
            float t11 = __shfl_sync(0xffffffffu, sf[kk][3], srcA);
            float t20 = __shfl_sync(0xffffffffu, sf[kk][0], srcB);
            float t21 = __shfl_sync(0xffffffffu, sf[kk][1], srcB);
            float t30 = __shfl_sync(0xffffffffu, sf[kk][2], srcB);
            float t31 = __shfl_sync(0xffffffffu, sf[kk][3], srcB);
            float a0 = odd ? t01 : t00;   // P[g   ][kk*8+qc]
            float a1 = odd ? t11 : t10;   // P[g+8 ][kk*8+qc]
            float a2 = odd ? t21 : t20;   // P[g   ][kk*8+qc+4]
            float a3 = odd ? t31 : t30;   // P[g+8 ][kk*8+qc+4]
#pragma unroll
            for (int nb2 = 0; nb2 < 10; nb2++) {
                float b0 = Vs[(kk * 8 + qc    ) * VST + nb2 * 8 + qr];
                float b1 = Vs[(kk * 8 + qc + 4) * VST + nb2 * 8 + qr];
                mma_tf32(of[nb2], a0, a1, a2, a3, b0, b1);
            }
        }
    }

    // Epilogue: normalize and store
    float inv0 = 1.0f / l0, inv1 = 1.0f / l1;
    float* og = g_attn + (size_t)(b * S_ + q0 + w * 16) * D_ + h * DH_;
#pragma unroll
    for (int nb2 = 0; nb2 < 10; nb2++) {
        int col = nb2 * 8 + qc * 2;
        *(float2*)(og + (qr    ) * D_ + col) =
            make_float2(of[nb2][0] * inv0, of[nb2][1] * inv0);
        *(float2*)(og + (qr + 8) * D_ + col) =
            make_float2(of[nb2][2] * inv1, of[nb2][3] * inv1);
    }
}

// ---------------------------------------------------------------------------
extern "C" void kernel_launch(void* const* d_in, const int* in_sizes, int n_in,
                              void* d_out, int out_size)
{
    const float* x   = (const float*)d_in[0];
    const float* enc = (const float*)d_in[1];
    const float* Wq  = (const float*)d_in[2];
    const float* Wk  = (const float*)d_in[3];
    const float* Wv  = (const float*)d_in[4];
    const float* Wo  = (const float*)d_in[5];
    const float* bo  = (const float*)d_in[6];
    float* out = (float*)d_out;

    float *qp, *kp, *vp, *ap;
    cudaGetSymbolAddress((void**)&qp, g_q);
    cudaGetSymbolAddress((void**)&kp, g_k);
    cudaGetSymbolAddress((void**)&vp, g_v);
    cudaGetSymbolAddress((void**)&ap, g_attn);

    dim3 gemm_grid(D_ / 64, M_ / 128);   // (10, 32)
    sgemm128x64<<<gemm_grid, 256>>>(x,   Wq, nullptr, qp, D_, D_);
    sgemm128x64<<<gemm_grid, 256>>>(enc, Wk, nullptr, kp, D_, D_);
    sgemm128x64<<<gemm_grid, 256>>>(enc, Wv, nullptr, vp, D_, D_);

    dim3 attn_grid(S_ / BMQ, H_, B_);    // (16, 8, 2)
    flash_attn_tc<<<attn_grid, 256>>>();

    sgemm128x64<<<gemm_grid, 256>>>(ap, Wo, bo, out, D_, D_);
}